// round 10
// baseline (speedup 1.0000x reference)
#include <cuda_runtime.h>
#include <cstdint>
#include <cstddef>

#define BB 16
#define SS 4096
#define DD 256
#define CL 8
#define NROWW 16
#define NTHREADS 544          // wid0=S(+stager), wid1..16 = 16 row warps
#define NB (SS / 4)
#define RING 32               // wv ring (steps)
#define RINGC 32              // cslot ring (steps)
#define XD 32                 // x smem ring depth (steps)
#define LAGF 16

typedef unsigned long long ull;

// per-(b,t): {q, q*P1, q*P2, q*P3}; q = c/alpha, Pk = x_t . x_{t+k}
__device__ float4 g_f4[BB * SS + 16];
__device__ float  g_d[BB * SS + 16];   // d = 2*alpha*c + c^2*||x||^2
__device__ float  g_G0;

// ---------------- helpers --------------------------------------------------
__device__ __forceinline__ ull mul2(ull a, ull b) {
    ull d; asm("mul.rn.f32x2 %0,%1,%2;" : "=l"(d) : "l"(a), "l"(b)); return d;
}
__device__ __forceinline__ ull fma2(ull a, ull b, ull c) {
    ull d; asm("fma.rn.f32x2 %0,%1,%2,%3;" : "=l"(d) : "l"(a), "l"(b), "l"(c)); return d;
}
__device__ __forceinline__ void unpk(ull a, float& x, float& y) {
    asm("mov.b64 {%0,%1},%2;" : "=f"(x), "=f"(y) : "l"(a));
}
__device__ __forceinline__ ull pk(float lo, float hi) {
    ull d; asm("mov.b64 %0,{%1,%2};" : "=l"(d) : "f"(lo), "f"(hi)); return d;
}
__device__ __forceinline__ ull pack_fu(float v, unsigned tag) {
    return (ull)__float_as_uint(v) | ((ull)tag << 32);
}
__device__ __forceinline__ ull ldsv64(uint32_t a) {
    ull v; asm volatile("ld.volatile.shared.b64 %0,[%1];" : "=l"(v) : "r"(a) : "memory"); return v;
}
__device__ __forceinline__ void stsv64(uint32_t a, ull v) {
    asm volatile("st.volatile.shared.b64 [%0],%1;" :: "r"(a), "l"(v) : "memory");
}
__device__ __forceinline__ unsigned ldsv32(uint32_t a) {
    unsigned v; asm volatile("ld.volatile.shared.b32 %0,[%1];" : "=r"(v) : "r"(a) : "memory"); return v;
}
__device__ __forceinline__ void stsv32(uint32_t a, unsigned v) {
    asm volatile("st.volatile.shared.b32 [%0],%1;" :: "r"(a), "r"(v) : "memory");
}
__device__ __forceinline__ void stcl64(uint32_t a, ull v) {
    asm volatile("st.shared::cluster.b64 [%0],%1;" :: "r"(a), "l"(v) : "memory");
}
__device__ __forceinline__ float poll_tag64(uint32_t a, unsigned want) {
    ull u = ldsv64(a);
    while ((unsigned)(u >> 32) != want) u = ldsv64(a);
    return __uint_as_float((unsigned)u);
}
__device__ __forceinline__ void poll_ge32(uint32_t a, int want) {
    while ((int)ldsv32(a) < want) { }
}
__device__ __forceinline__ void cpa16(uint32_t d, const void* s) {
    asm volatile("cp.async.ca.shared.global [%0],[%1],16;" :: "r"(d), "l"(s));
}
__device__ __forceinline__ float wredux(float v) {
    #pragma unroll
    for (int k = 16; k; k >>= 1) v += __shfl_xor_sync(0xffffffffu, v, k);
    return v;
}

// ---------------------------------------------------------------------------
__global__ void coef_kernel(const float* __restrict__ x,
                            const float* __restrict__ eta_raw,
                            const float* __restrict__ alpha_raw) {
    float eta   = 0.2f / (1.0f + __expf(-eta_raw[0]));
    float alpha = 0.5f + 0.5f / (1.0f + __expf(-alpha_raw[0]));
    int warp  = (blockIdx.x * blockDim.x + threadIdx.x) >> 5;
    int lane  = threadIdx.x & 31;
    int nwarp = (gridDim.x * blockDim.x) >> 5;
    int ngrp  = BB * (SS / 4);
    for (int grp = warp; grp < ngrp; grp += nwarp) {
        int b  = grp / (SS / 4);
        int t0 = (grp % (SS / 4)) * 4;
        const float* base = x + ((size_t)b * SS + t0) * DD;
        float4 R[7][2];
        #pragma unroll
        for (int r = 0; r < 7; r++) {
            int tr = t0 + r; if (tr > SS - 1) tr = SS - 1;
            const float4* p = reinterpret_cast<const float4*>(base + (size_t)(tr - t0) * DD);
            R[r][0] = p[lane]; R[r][1] = p[lane + 32];
        }
        float dv[16];
        #pragma unroll
        for (int i = 0; i < 4; i++) {
            #pragma unroll
            for (int k = 0; k < 4; k++) {
                float4 a0 = R[i][0], a1 = R[i][1];
                float4 b0 = R[i + k][0], b1 = R[i + k][1];
                dv[i * 4 + k] = a0.x*b0.x + a0.y*b0.y + a0.z*b0.z + a0.w*b0.w
                              + a1.x*b1.x + a1.y*b1.y + a1.z*b1.z + a1.w*b1.w;
            }
        }
        #pragma unroll
        for (int kk = 16; kk; kk >>= 1)
            #pragma unroll
            for (int i = 0; i < 16; i++) dv[i] += __shfl_xor_sync(0xffffffffu, dv[i], kk);
        if (lane == 0) {
            #pragma unroll
            for (int i = 0; i < 4; i++) {
                float ss  = dv[i * 4];
                float n   = fmaxf(sqrtf(ss), 1e-6f);
                float inv = 1.0f / n;
                float c   = eta * (1.0f - inv) * inv;
                float q   = c / alpha;
                float4 o;
                o.x = q;
                o.y = q * dv[i * 4 + 1];
                o.z = q * dv[i * 4 + 2];
                o.w = q * dv[i * 4 + 3];
                g_f4[(size_t)b * SS + t0 + i] = o;
                g_d [(size_t)b * SS + t0 + i] = 2.0f * alpha * c + c * c * ss;
            }
        }
    }
}

__global__ void g0_kernel(const float* __restrict__ M) {
    __shared__ float red[32];
    int tid = threadIdx.x;
    float s = 0.0f;
    for (int i = tid; i < DD * DD; i += 1024) { float v = M[i]; s = fmaf(v, v, s); }
    s = wredux(s);
    if ((tid & 31) == 0) red[tid >> 5] = s;
    __syncthreads();
    if (tid < 32) {
        float v = red[tid];
        v = wredux(v);
        if (tid == 0) g_G0 = v;
    }
}

// ---------------------------------------------------------------------------
// 8-CTA cluster per batch. No G warp.
//   wid 0 (S): stages x+f4 (cp.async, lead 16); phase A(t): poll own wv,
//              local ||w||^2, DSMEM-push to 8 CTAs; phase B(t-2): consume
//              peers, scalar recurrence, coalesced outputs, fold factors.
//   wid 1-16 : row warps, 2 rows each, 4-step blocked triangular scheme,
//              x loaded ONCE per block from smem into regs.
// ---------------------------------------------------------------------------
__global__ void __cluster_dims__(CL, 1, 1) __launch_bounds__(NTHREADS, 1)
scan_kernel(const float* __restrict__ x,
            const float* __restrict__ Minit,
            const float* __restrict__ alpha_raw,
            float* __restrict__ out) {
    __shared__ __align__(16) float  xs[XD][DD];     // 32 KB x ring
    __shared__ __align__(16) float4 f4s[XD];        // 512 B
    __shared__ ull wv[RING][32];      // 8 KB {tag, w_row true-scale}
    __shared__ ull cslot[RINGC][CL];  // 2 KB {tag, CTA partial} (DSMEM in)
    __shared__ ull resf[8];
    __shared__ ull finslot;
    __shared__ unsigned xprog;

    unsigned rank; asm("mov.u32 %0, %%cluster_ctarank;" : "=r"(rank));
    int batch = blockIdx.x / CL;
    int tid   = threadIdx.x;
    int wid   = tid >> 5;
    int lane  = tid & 31;

    for (int i = tid; i < RING * 32;   i += NTHREADS) (&wv[0][0])[i]    = 0ull;
    for (int i = tid; i < RINGC * CL;  i += NTHREADS) (&cslot[0][0])[i] = 0ull;
    if (tid < 8)  resf[tid] = 0ull;
    if (tid == 0) { finslot = 0ull; xprog = 0u; }
    __syncthreads();
    asm volatile("barrier.cluster.arrive.aligned;" ::: "memory");
    asm volatile("barrier.cluster.wait.aligned;"   ::: "memory");

    float alpha = 0.5f + 0.5f / (1.0f + __expf(-alpha_raw[0]));

    uint32_t wv_b  = (uint32_t)__cvta_generic_to_shared(&wv[0][0]);
    uint32_t cs_b  = (uint32_t)__cvta_generic_to_shared(&cslot[0][0]);
    uint32_t rf_b  = (uint32_t)__cvta_generic_to_shared(&resf[0]);
    uint32_t fin_b = (uint32_t)__cvta_generic_to_shared(&finslot);
    uint32_t xp_b  = (uint32_t)__cvta_generic_to_shared(&xprog);

    if (wid >= 1) {
        // ===================== row warp: 4-step blocks =====================
        int rw  = wid - 1;
        int rg0 = (int)rank * 32 + rw * 2;
        float al1 = alpha, al2 = alpha * alpha;
        float al3 = al2 * alpha, al4 = al2 * al2;

        ull m0[4], m1[4];
        {
            const ulonglong2* mp = (const ulonglong2*)Minit + (size_t)rg0 * 64;
            ulonglong2 v0 = mp[lane],      v1 = mp[32 + lane];
            m0[0] = v0.x; m0[1] = v0.y; m0[2] = v1.x; m0[3] = v1.y;
            v0 = mp[64 + lane]; v1 = mp[96 + lane];
            m1[0] = v0.x; m1[1] = v0.y; m1[2] = v1.x; m1[3] = v1.y;
        }
        const ulonglong2* xsp = (const ulonglong2*)&xs[0][0];
        uint32_t wv_me = wv_b + (uint32_t)(rw * 2 + (lane >> 4)) * 8u;
        int h = lane >> 4;
        float a_k = 1.0f;

        for (int blk = 0; blk < NB; blk++) {
            int t0 = blk * 4;
            poll_ge32(xp_b, t0 + 4);
            // load block x into registers (once; both passes from regs)
            ull xr[4][4];
            #pragma unroll
            for (int j = 0; j < 4; j++) {
                int sl = (t0 + j) & (XD - 1);
                ulonglong2 v0 = xsp[sl * 64 + lane], v1 = xsp[sl * 64 + 32 + lane];
                xr[j][0] = v0.x; xr[j][1] = v0.y; xr[j][2] = v1.x; xr[j][3] = v1.y;
            }
            float4 f0 = f4s[(t0 + 0) & (XD - 1)];
            float4 f1 = f4s[(t0 + 1) & (XD - 1)];
            float4 f2 = f4s[(t0 + 2) & (XD - 1)];
            float4 f3 = f4s[(t0 + 3) & (XD - 1)];

            // 8 independent dots vs frozen m~
            float r[8];
            #pragma unroll
            for (int j = 0; j < 4; j++) {
                ull a = mul2(m0[0], xr[j][0]);
                a = fma2(m0[1], xr[j][1], a); a = fma2(m0[2], xr[j][2], a); a = fma2(m0[3], xr[j][3], a);
                ull b = mul2(m1[0], xr[j][0]);
                b = fma2(m1[1], xr[j][1], b); b = fma2(m1[2], xr[j][2], b); b = fma2(m1[3], xr[j][3], b);
                float ax, ay, bx, by; unpk(a, ax, ay); unpk(b, bx, by);
                r[2 * j]     = ax + ay;
                r[2 * j + 1] = bx + by;
            }
            #pragma unroll
            for (int k = 16; k; k >>= 1)
                #pragma unroll
                for (int i = 0; i < 8; i++) r[i] += __shfl_xor_sync(0xffffffffu, r[i], k);

            // exact triangular recurrence
            float wa0 = r[0], wb0 = r[1];
            float wa1 = fmaf(f0.y, wa0, r[2]);
            float wb1 = fmaf(f0.y, wb0, r[3]);
            float wa2 = fmaf(f0.z, wa0, fmaf(f1.y, wa1, r[4]));
            float wb2 = fmaf(f0.z, wb0, fmaf(f1.y, wb1, r[5]));
            float wa3 = fmaf(f0.w, wa0, fmaf(f1.z, wa1, fmaf(f2.y, wa2, r[6])));
            float wb3 = fmaf(f0.w, wb0, fmaf(f1.z, wb1, fmaf(f2.y, wb2, r[7])));

            // true scale + post w (lanes 0 and 16)
            float ta0 = a_k * wa0,        tb0 = a_k * wb0;
            float ta1 = a_k * al1 * wa1,  tb1 = a_k * al1 * wb1;
            float ta2 = a_k * al2 * wa2,  tb2 = a_k * al2 * wb2;
            float ta3 = a_k * al3 * wa3,  tb3 = a_k * al3 * wb3;
            if ((lane & 15) == 0) {
                float p0 = h ? tb0 : ta0, p1 = h ? tb1 : ta1;
                float p2 = h ? tb2 : ta2, p3 = h ? tb3 : ta3;
                stsv64(wv_me + (uint32_t)((t0 + 0) & (RING - 1)) * 256u, pack_fu(p0, t0 + 1));
                stsv64(wv_me + (uint32_t)((t0 + 1) & (RING - 1)) * 256u, pack_fu(p1, t0 + 2));
                stsv64(wv_me + (uint32_t)((t0 + 2) & (RING - 1)) * 256u, pack_fu(p2, t0 + 3));
                stsv64(wv_me + (uint32_t)((t0 + 3) & (RING - 1)) * 256u, pack_fu(p3, t0 + 4));
            }

            // 4 rank-1 updates
            float ga[4], gb[4];
            ga[0] = f0.x * wa0; gb[0] = f0.x * wb0;
            ga[1] = f1.x * wa1; gb[1] = f1.x * wb1;
            ga[2] = f2.x * wa2; gb[2] = f2.x * wb2;
            ga[3] = f3.x * wa3; gb[3] = f3.x * wb3;
            #pragma unroll
            for (int j = 0; j < 4; j++) {
                ull g2a = pk(ga[j], ga[j]), g2b = pk(gb[j], gb[j]);
                m0[0] = fma2(g2a, xr[j][0], m0[0]); m0[1] = fma2(g2a, xr[j][1], m0[1]);
                m0[2] = fma2(g2a, xr[j][2], m0[2]); m0[3] = fma2(g2a, xr[j][3], m0[3]);
                m1[0] = fma2(g2b, xr[j][0], m1[0]); m1[1] = fma2(g2b, xr[j][1], m1[1]);
                m1[2] = fma2(g2b, xr[j][2], m1[2]); m1[3] = fma2(g2b, xr[j][3], m1[3]);
            }
            a_k *= al4;

            // scheduled fold (identical to R9 schedule; PASSED accounting)
            if ((t0 & 31) == 12 && t0 >= 44) {
                int jj = (t0 - 44) >> 5;
                float f = 0.0f;
                if (lane == 0)
                    f = poll_tag64(rf_b + (uint32_t)(jj & 7) * 8u, (unsigned)(jj + 1));
                f = __shfl_sync(0xffffffffu, f, 0);
                float F = f * a_k;
                ull F2 = pk(F, F);
                #pragma unroll
                for (int j = 0; j < 4; j++) { m0[j] = mul2(F2, m0[j]); m1[j] = mul2(F2, m1[j]); }
                a_k = 1.0f;
            }
        }
        // M_final
        float Pf = 0.0f;
        if (lane == 0) Pf = poll_tag64(fin_b, 0x7fffffffu);
        Pf = __shfl_sync(0xffffffffu, Pf, 0);
        float fs = Pf * a_k;
        ull p2 = pk(fs, fs);
        ulonglong2* mo = (ulonglong2*)
            (out + (size_t)BB * SS * DD + (size_t)batch * DD * DD) + (size_t)rg0 * 64;
        ulonglong2 sv;
        sv.x = mul2(p2, m0[0]); sv.y = mul2(p2, m0[1]); mo[lane]      = sv;
        sv.x = mul2(p2, m0[2]); sv.y = mul2(p2, m0[3]); mo[32 + lane] = sv;
        sv.x = mul2(p2, m1[0]); sv.y = mul2(p2, m1[1]); mo[64 + lane] = sv;
        sv.x = mul2(p2, m1[2]); sv.y = mul2(p2, m1[3]); mo[96 + lane] = sv;

    } else {
        // ===================== S warp (stager + scalar engine) =============
        const char*   xsrc = (const char*)(x + (size_t)batch * SS * DD);
        const float4* fsrc = g_f4 + (size_t)batch * SS;
        const float*  db   = g_d  + (size_t)batch * SS;
        uint32_t xs_b = (uint32_t)__cvta_generic_to_shared(&xs[0][0]);
        uint32_t f4_b = (uint32_t)__cvta_generic_to_shared(&f4s[0]);
        uint32_t raddr = 0;
        {
            uint32_t cb2 = (uint32_t)__cvta_generic_to_shared(&cslot[0][rank]);
            if (lane < CL)
                asm("mapa.shared::cluster.u32 %0,%1,%2;" : "=r"(raddr) : "r"(cb2), "r"(lane));
        }
        // prologue: stage steps 0..15 (one commit group each)
        #pragma unroll
        for (int l = 0; l < 16; l++) {
            uint32_t dst = xs_b + (uint32_t)(l & (XD - 1)) * 1024u + (uint32_t)lane * 16u;
            const char* src = xsrc + (size_t)l * 1024 + lane * 16;
            cpa16(dst, src);
            cpa16(dst + 512u, src + 512);
            if (lane == 0) cpa16(f4_b + (uint32_t)(l & (XD - 1)) * 16u, fsrc + l);
            asm volatile("cp.async.commit_group;" ::: "memory");
        }

        float P = 1.0f, G = g_G0;
        float aa = alpha * alpha;
        float pend_f = 1.0f; int pend_mat = -1;
        float w0r = 0.0f, w1r = 0.0f, w2r = 0.0f, w3r = 0.0f;  // w history
        float* outb = out + (size_t)batch * SS * DD + rank * 32 + lane;

        for (int tau = 0; tau < SS + 2; tau++) {
            // --- stage step tau+16 (clamped), publish xprog = tau+11 ---
            {
                int l = tau + 16; int ls = (l > SS - 1) ? SS - 1 : l;
                uint32_t dst = xs_b + (uint32_t)(l & (XD - 1)) * 1024u + (uint32_t)lane * 16u;
                const char* src = xsrc + (size_t)ls * 1024 + lane * 16;
                cpa16(dst, src);
                cpa16(dst + 512u, src + 512);
                if (lane == 0) cpa16(f4_b + (uint32_t)(l & (XD - 1)) * 16u, fsrc + ls);
                asm volatile("cp.async.commit_group;" ::: "memory");
                asm volatile("cp.async.wait_group 6;" ::: "memory");
                asm volatile("membar.cta;" ::: "memory");
                if (lane == 0) stsv32(xp_b, (unsigned)(tau + 11));
            }
            // rotate w history
            w3r = w2r; w2r = w1r; w1r = w0r;
            // --- phase A(tau): poll own wv, local partial, push to 8 CTAs ---
            if (tau < SS) {
                int slot = tau & (RING - 1);
                float w = poll_tag64(wv_b + (uint32_t)(slot * 32 + lane) * 8u, (unsigned)(tau + 1));
                w0r = w;
                float zl = wredux(w * w);
                if (lane < CL)
                    stcl64(raddr + (uint32_t)(tau & (RINGC - 1)) * (CL * 8u),
                           pack_fu(zl, (unsigned)(tau + 1)));
            }
            // --- phase B(tb = tau-2): consume peers, recurrence, output ---
            if (tau >= 2) {
                int tb = tau - 2;
                float zc = 0.0f;
                if (lane < CL)
                    zc = poll_tag64(cs_b + (uint32_t)((tb & (RINGC - 1)) * CL + lane) * 8u,
                                    (unsigned)(tb + 1));
                zc = wredux(zc);
                float w  = w2r;
                float Qb = P;
                outb[(size_t)tb * DD] = Qb * w;
                float y2 = Qb * Qb * zc;
                float d  = __ldg(db + tb);
                float Gn = fmaf(aa, G, d * y2);
                float s  = fminf(15.0f / (sqrtf(Gn) + 1e-6f), 1.0f);
                G = s * s * Gn;
                P = Qb * s;
                if (tb == pend_mat) { P = P / pend_f; pend_mat = -1; }
                if ((tb & 31) == 31 && tb + LAGF <= SS - 1) {
                    int jj = tb >> 5;
                    pend_f = P;
                    pend_mat = tb + LAGF;
                    if (lane == 0)
                        stsv64(rf_b + (uint32_t)(jj & 7) * 8u, pack_fu(P, (unsigned)(jj + 1)));
                }
            }
        }
        if (lane == 0) stsv64(fin_b, pack_fu(P, 0x7fffffffu));
    }
}

// ---------------------------------------------------------------------------
extern "C" void kernel_launch(void* const* d_in, const int* in_sizes, int n_in,
                              void* d_out, int out_size) {
    const float* x         = (const float*)d_in[0];
    const float* M_init    = (const float*)d_in[1];
    const float* eta_raw   = (const float*)d_in[2];
    const float* alpha_raw = (const float*)d_in[3];
    float*       out       = (float*)d_out;

    coef_kernel<<<1024, 256>>>(x, eta_raw, alpha_raw);
    g0_kernel<<<1, 1024>>>(M_init);
    scan_kernel<<<BB * CL, NTHREADS>>>(x, M_init, alpha_raw, out);
}

// round 16
// speedup vs baseline: 1.4958x; 1.4958x over previous
#include <cuda_runtime.h>
#include <cstdint>
#include <cstddef>

#define BB 16
#define SS 4096
#define DD 256
#define CL 8
#define NW 20                 // warps: 0=L 1=Z 2=P 3=O 4..19=rows
#define NTHREADS 640
#define NBLK (SS / 4)
#define XD 16                 // x smem ring (steps)
#define RWV 64                // wv / qring rings (steps)
#define RZ 32                 // zv / cslot rings (steps)
#define LAGF 16

typedef unsigned long long ull;

// per-(b,t): {q, q*P1, q*P2, q*P3}; q = c/alpha, Pk = x_t . x_{t+k}
__device__ float4 g_f4[BB * SS + 16];
__device__ float  g_d[BB * SS + 16];

// ---------------- helpers --------------------------------------------------
__device__ __forceinline__ ull mul2(ull a, ull b) {
    ull d; asm("mul.rn.f32x2 %0,%1,%2;" : "=l"(d) : "l"(a), "l"(b)); return d;
}
__device__ __forceinline__ ull fma2(ull a, ull b, ull c) {
    ull d; asm("fma.rn.f32x2 %0,%1,%2,%3;" : "=l"(d) : "l"(a), "l"(b), "l"(c)); return d;
}
__device__ __forceinline__ void unpk(ull a, float& x, float& y) {
    asm("mov.b64 {%0,%1},%2;" : "=f"(x), "=f"(y) : "l"(a));
}
__device__ __forceinline__ ull pk(float lo, float hi) {
    ull d; asm("mov.b64 %0,{%1,%2};" : "=l"(d) : "f"(lo), "f"(hi)); return d;
}
__device__ __forceinline__ ull pack_fu(float v, unsigned tag) {
    return (ull)__float_as_uint(v) | ((ull)tag << 32);
}
__device__ __forceinline__ ull ldsv64(uint32_t a) {
    ull v; asm volatile("ld.volatile.shared.b64 %0,[%1];" : "=l"(v) : "r"(a) : "memory"); return v;
}
__device__ __forceinline__ void ldsv128(uint32_t a, ull& lo, ull& hi) {
    asm volatile("ld.volatile.shared.v2.u64 {%0,%1},[%2];"
                 : "=l"(lo), "=l"(hi) : "r"(a) : "memory");
}
__device__ __forceinline__ void stsv64(uint32_t a, ull v) {
    asm volatile("st.volatile.shared.b64 [%0],%1;" :: "r"(a), "l"(v) : "memory");
}
__device__ __forceinline__ unsigned ldsv32(uint32_t a) {
    unsigned v; asm volatile("ld.volatile.shared.b32 %0,[%1];" : "=r"(v) : "r"(a) : "memory"); return v;
}
__device__ __forceinline__ void stsv32(uint32_t a, unsigned v) {
    asm volatile("st.volatile.shared.b32 [%0],%1;" :: "r"(a), "r"(v) : "memory");
}
__device__ __forceinline__ void stcl64(uint32_t a, ull v) {
    asm volatile("st.shared::cluster.b64 [%0],%1;" :: "r"(a), "l"(v) : "memory");
}
__device__ __forceinline__ float poll_tag64(uint32_t a, unsigned want) {
    ull u = ldsv64(a);
    while ((unsigned)(u >> 32) != want) u = ldsv64(a);
    return __uint_as_float((unsigned)u);
}
__device__ __forceinline__ void poll_ge32(uint32_t a, int want) {
    while ((int)ldsv32(a) < want) { }
}
__device__ __forceinline__ void cpa16(uint32_t d, const void* s) {
    asm volatile("cp.async.ca.shared.global [%0],[%1],16;" :: "r"(d), "l"(s));
}
__device__ __forceinline__ float wredux(float v) {
    #pragma unroll
    for (int k = 16; k; k >>= 1) v += __shfl_xor_sync(0xffffffffu, v, k);
    return v;
}

// ---------------------------------------------------------------------------
// Single fused kernel, 8-CTA cluster per batch. Phase 1: in-kernel g0 + coef
// tables. Phase 2 scan: L stager / Z gatherer / P scalar engine / O writer /
// 16 row warps.
// R16 fixes (vs R15): L stages group g only when pprog >= 4g-12 — proves all
// rows finished READING the x-slots that group g aliases (XD=16). O reads wv
// with a tagged poll. Ring bounds: rows <= P+8, P <= O+51 => rows <= O+59 < 64.
// ---------------------------------------------------------------------------
__global__ void __cluster_dims__(CL, 1, 1) __launch_bounds__(NTHREADS, 1)
fused_kernel(const float* __restrict__ x,
             const float* __restrict__ Minit,
             const float* __restrict__ eta_raw,
             const float* __restrict__ alpha_raw,
             float* __restrict__ out) {
    __shared__ __align__(16) float  xs[XD][DD];     // 16 KB
    __shared__ __align__(16) float4 f4s[XD];
    __shared__ ull wv[RWV][32];     // 16 KB {tag, w_row true-scale}
    __shared__ ull zv[RZ][16];      // 4 KB {tag, per-rowwarp ||w||^2 pair}
    __shared__ __align__(16) ull cslot[RZ][CL];  // 2 KB {tag, CTA partial}
    __shared__ ull qring[RWV];      // 512 B {tag, Q_t}
    __shared__ ull resf[8];
    __shared__ ull finslot;
    __shared__ unsigned xprog, pprog, oprog;
    __shared__ float sg[NW];
    __shared__ float g0v;

    unsigned rank; asm("mov.u32 %0, %%cluster_ctarank;" : "=r"(rank));
    int batch = blockIdx.x / CL;
    int tid   = threadIdx.x;
    int wid   = tid >> 5;
    int lane  = tid & 31;

    // ---- init mailboxes ----
    for (int i = tid; i < RWV * 32; i += NTHREADS) (&wv[0][0])[i]    = 0ull;
    for (int i = tid; i < RZ * 16;  i += NTHREADS) (&zv[0][0])[i]    = 0ull;
    for (int i = tid; i < RZ * CL;  i += NTHREADS) (&cslot[0][0])[i] = 0ull;
    for (int i = tid; i < RWV;      i += NTHREADS) qring[i] = 0ull;
    if (tid < 8)  resf[tid] = 0ull;
    if (tid == 0) { finslot = 0ull; xprog = 0u; pprog = 0u; oprog = 0u; }

    float eta   = 0.2f / (1.0f + __expf(-eta_raw[0]));
    float alpha = 0.5f + 0.5f / (1.0f + __expf(-alpha_raw[0]));

    // ---- g0 = ||M_init||^2 (redundant per CTA, deterministic order) ----
    {
        float s = 0.0f;
        for (int i = tid; i < DD * DD; i += NTHREADS) { float v = Minit[i]; s = fmaf(v, v, s); }
        s = wredux(s);
        if (lane == 0) sg[wid] = s;
    }
    __syncthreads();
    if (wid == 0) {
        float v = (lane < NW) ? sg[lane] : 0.0f;
        v = wredux(v);
        if (lane == 0) g0v = v;
    }

    // ---- coef phase: cluster computes its batch's f4/d tables ----
    {
        const float* xb = x + (size_t)batch * SS * DD;
        for (int i = 0; ; i++) {
            int g = (int)rank + CL * (wid + NW * i);
            if (g >= NBLK) break;
            int t0 = g * 4;
            float4 R[7][2];
            #pragma unroll
            for (int r = 0; r < 7; r++) {
                int tr = t0 + r; if (tr > SS - 1) tr = SS - 1;
                const float4* p = reinterpret_cast<const float4*>(xb + (size_t)tr * DD);
                R[r][0] = p[lane]; R[r][1] = p[lane + 32];
            }
            float dv[16];
            #pragma unroll
            for (int ii = 0; ii < 4; ii++) {
                #pragma unroll
                for (int k = 0; k < 4; k++) {
                    float4 a0 = R[ii][0], a1 = R[ii][1];
                    float4 b0 = R[ii + k][0], b1 = R[ii + k][1];
                    dv[ii * 4 + k] = a0.x*b0.x + a0.y*b0.y + a0.z*b0.z + a0.w*b0.w
                                   + a1.x*b1.x + a1.y*b1.y + a1.z*b1.z + a1.w*b1.w;
                }
            }
            #pragma unroll
            for (int kk = 16; kk; kk >>= 1)
                #pragma unroll
                for (int ii = 0; ii < 16; ii++) dv[ii] += __shfl_xor_sync(0xffffffffu, dv[ii], kk);
            if (lane == 0) {
                #pragma unroll
                for (int ii = 0; ii < 4; ii++) {
                    float ss  = dv[ii * 4];
                    float n   = fmaxf(sqrtf(ss), 1e-6f);
                    float inv = 1.0f / n;
                    float c   = eta * (1.0f - inv) * inv;
                    float q   = c / alpha;
                    float4 o;
                    o.x = q;
                    o.y = q * dv[ii * 4 + 1];
                    o.z = q * dv[ii * 4 + 2];
                    o.w = q * dv[ii * 4 + 3];
                    g_f4[(size_t)batch * SS + t0 + ii] = o;
                    g_d [(size_t)batch * SS + t0 + ii] = 2.0f * alpha * c + c * c * ss;
                }
            }
        }
    }
    __threadfence();
    __syncthreads();
    asm volatile("barrier.cluster.arrive.aligned;" ::: "memory");
    asm volatile("barrier.cluster.wait.aligned;"   ::: "memory");

    uint32_t wv_b  = (uint32_t)__cvta_generic_to_shared(&wv[0][0]);
    uint32_t zv_b  = (uint32_t)__cvta_generic_to_shared(&zv[0][0]);
    uint32_t cs_b  = (uint32_t)__cvta_generic_to_shared(&cslot[0][0]);
    uint32_t qr_b  = (uint32_t)__cvta_generic_to_shared(&qring[0]);
    uint32_t rf_b  = (uint32_t)__cvta_generic_to_shared(&resf[0]);
    uint32_t fin_b = (uint32_t)__cvta_generic_to_shared(&finslot);
    uint32_t xp_b  = (uint32_t)__cvta_generic_to_shared(&xprog);
    uint32_t pp_b  = (uint32_t)__cvta_generic_to_shared(&pprog);
    uint32_t op_b  = (uint32_t)__cvta_generic_to_shared(&oprog);

    if (wid >= 4) {
        // ===================== row warp: 4-step blocks =====================
        int rw  = wid - 4;
        int rg0 = (int)rank * 32 + rw * 2;
        float al1 = alpha, al2 = alpha * alpha;
        float al3 = al2 * alpha, al4 = al2 * al2;

        ull m0[4], m1[4];
        {
            const ulonglong2* mp = (const ulonglong2*)Minit + (size_t)rg0 * 64;
            ulonglong2 v0 = mp[lane],      v1 = mp[32 + lane];
            m0[0] = v0.x; m0[1] = v0.y; m0[2] = v1.x; m0[3] = v1.y;
            v0 = mp[64 + lane]; v1 = mp[96 + lane];
            m1[0] = v0.x; m1[1] = v0.y; m1[2] = v1.x; m1[3] = v1.y;
        }
        const ulonglong2* xsp = (const ulonglong2*)&xs[0][0];
        uint32_t wv_me = wv_b + (uint32_t)(rw * 2 + (lane >> 4)) * 8u;
        uint32_t zv_me = zv_b + (uint32_t)rw * 8u;
        int h = lane >> 4;
        float a_k = 1.0f;

        for (int blk = 0; blk < NBLK; blk++) {
            int t0 = blk * 4;
            poll_ge32(xp_b, t0 + 4);
            ull xr[4][4];
            #pragma unroll
            for (int j = 0; j < 4; j++) {
                int sl = (t0 + j) & (XD - 1);
                ulonglong2 v0 = xsp[sl * 64 + lane], v1 = xsp[sl * 64 + 32 + lane];
                xr[j][0] = v0.x; xr[j][1] = v0.y; xr[j][2] = v1.x; xr[j][3] = v1.y;
            }
            float4 f0 = f4s[(t0 + 0) & (XD - 1)];
            float4 f1 = f4s[(t0 + 1) & (XD - 1)];
            float4 f2 = f4s[(t0 + 2) & (XD - 1)];
            float4 f3 = f4s[(t0 + 3) & (XD - 1)];

            float r[8];
            #pragma unroll
            for (int j = 0; j < 4; j++) {
                ull a = mul2(m0[0], xr[j][0]);
                a = fma2(m0[1], xr[j][1], a); a = fma2(m0[2], xr[j][2], a); a = fma2(m0[3], xr[j][3], a);
                ull b = mul2(m1[0], xr[j][0]);
                b = fma2(m1[1], xr[j][1], b); b = fma2(m1[2], xr[j][2], b); b = fma2(m1[3], xr[j][3], b);
                float ax, ay, bx, by; unpk(a, ax, ay); unpk(b, bx, by);
                r[2 * j]     = ax + ay;
                r[2 * j + 1] = bx + by;
            }
            #pragma unroll
            for (int k = 16; k; k >>= 1)
                #pragma unroll
                for (int i = 0; i < 8; i++) r[i] += __shfl_xor_sync(0xffffffffu, r[i], k);

            float wa0 = r[0], wb0 = r[1];
            float wa1 = fmaf(f0.y, wa0, r[2]);
            float wb1 = fmaf(f0.y, wb0, r[3]);
            float wa2 = fmaf(f0.z, wa0, fmaf(f1.y, wa1, r[4]));
            float wb2 = fmaf(f0.z, wb0, fmaf(f1.y, wb1, r[5]));
            float wa3 = fmaf(f0.w, wa0, fmaf(f1.z, wa1, fmaf(f2.y, wa2, r[6])));
            float wb3 = fmaf(f0.w, wb0, fmaf(f1.z, wb1, fmaf(f2.y, wb2, r[7])));

            float ta0 = a_k * wa0,        tb0 = a_k * wb0;
            float ta1 = a_k * al1 * wa1,  tb1 = a_k * al1 * wb1;
            float ta2 = a_k * al2 * wa2,  tb2 = a_k * al2 * wb2;
            float ta3 = a_k * al3 * wa3,  tb3 = a_k * al3 * wb3;
            if ((lane & 15) == 0) {
                float p0 = h ? tb0 : ta0, p1 = h ? tb1 : ta1;
                float p2 = h ? tb2 : ta2, p3 = h ? tb3 : ta3;
                stsv64(wv_me + (uint32_t)((t0 + 0) & (RWV - 1)) * 256u, pack_fu(p0, t0 + 1));
                stsv64(wv_me + (uint32_t)((t0 + 1) & (RWV - 1)) * 256u, pack_fu(p1, t0 + 2));
                stsv64(wv_me + (uint32_t)((t0 + 2) & (RWV - 1)) * 256u, pack_fu(p2, t0 + 3));
                stsv64(wv_me + (uint32_t)((t0 + 3) & (RWV - 1)) * 256u, pack_fu(p3, t0 + 4));
            }
            if (lane == 0) {
                stsv64(zv_me + (uint32_t)((t0 + 0) & (RZ - 1)) * 128u, pack_fu(fmaf(ta0, ta0, tb0 * tb0), t0 + 1));
                stsv64(zv_me + (uint32_t)((t0 + 1) & (RZ - 1)) * 128u, pack_fu(fmaf(ta1, ta1, tb1 * tb1), t0 + 2));
                stsv64(zv_me + (uint32_t)((t0 + 2) & (RZ - 1)) * 128u, pack_fu(fmaf(ta2, ta2, tb2 * tb2), t0 + 3));
                stsv64(zv_me + (uint32_t)((t0 + 3) & (RZ - 1)) * 128u, pack_fu(fmaf(ta3, ta3, tb3 * tb3), t0 + 4));
            }

            float ga[4], gb[4];
            ga[0] = f0.x * wa0; gb[0] = f0.x * wb0;
            ga[1] = f1.x * wa1; gb[1] = f1.x * wb1;
            ga[2] = f2.x * wa2; gb[2] = f2.x * wb2;
            ga[3] = f3.x * wa3; gb[3] = f3.x * wb3;
            #pragma unroll
            for (int j = 0; j < 4; j++) {
                ull g2a = pk(ga[j], ga[j]), g2b = pk(gb[j], gb[j]);
                m0[0] = fma2(g2a, xr[j][0], m0[0]); m0[1] = fma2(g2a, xr[j][1], m0[1]);
                m0[2] = fma2(g2a, xr[j][2], m0[2]); m0[3] = fma2(g2a, xr[j][3], m0[3]);
                m1[0] = fma2(g2b, xr[j][0], m1[0]); m1[1] = fma2(g2b, xr[j][1], m1[1]);
                m1[2] = fma2(g2b, xr[j][2], m1[2]); m1[3] = fma2(g2b, xr[j][3], m1[3]);
            }
            a_k *= al4;

            if ((t0 & 31) == 12 && t0 >= 44) {
                int jj = (t0 - 44) >> 5;
                float f = 0.0f;
                if (lane == 0)
                    f = poll_tag64(rf_b + (uint32_t)(jj & 7) * 8u, (unsigned)(jj + 1));
                f = __shfl_sync(0xffffffffu, f, 0);
                float F = f * a_k;
                ull F2 = pk(F, F);
                #pragma unroll
                for (int j = 0; j < 4; j++) { m0[j] = mul2(F2, m0[j]); m1[j] = mul2(F2, m1[j]); }
                a_k = 1.0f;
            }
        }
        float Pf = 0.0f;
        if (lane == 0) Pf = poll_tag64(fin_b, 0x7fffffffu);
        Pf = __shfl_sync(0xffffffffu, Pf, 0);
        float fs = Pf * a_k;
        ull p2 = pk(fs, fs);
        ulonglong2* mo = (ulonglong2*)
            (out + (size_t)BB * SS * DD + (size_t)batch * DD * DD) + (size_t)rg0 * 64;
        ulonglong2 sv;
        sv.x = mul2(p2, m0[0]); sv.y = mul2(p2, m0[1]); mo[lane]      = sv;
        sv.x = mul2(p2, m0[2]); sv.y = mul2(p2, m0[3]); mo[32 + lane] = sv;
        sv.x = mul2(p2, m1[0]); sv.y = mul2(p2, m1[1]); mo[64 + lane] = sv;
        sv.x = mul2(p2, m1[2]); sv.y = mul2(p2, m1[3]); mo[96 + lane] = sv;

    } else if (wid == 0) {
        // ===================== L: x + f4 stager =====================
        const char*   xsrc = (const char*)(x + (size_t)batch * SS * DD);
        const float4* fsrc = g_f4 + (size_t)batch * SS;
        uint32_t xs_b = (uint32_t)__cvta_generic_to_shared(&xs[0][0]);
        uint32_t f4_b = (uint32_t)__cvta_generic_to_shared(&f4s[0]);
        #pragma unroll
        for (int g = 0; g < 4; g++) {
            #pragma unroll
            for (int j = 0; j < 4; j++) {
                int l = g * 4 + j;
                uint32_t dst = xs_b + (uint32_t)(l & (XD - 1)) * 1024u + (uint32_t)lane * 16u;
                const char* src = xsrc + (size_t)l * 1024 + lane * 16;
                cpa16(dst, src);
                cpa16(dst + 512u, src + 512);
            }
            if (lane < 4) {
                int l = g * 4 + lane;
                cpa16(f4_b + (uint32_t)(l & (XD - 1)) * 16u, fsrc + l);
            }
            asm volatile("cp.async.commit_group;" ::: "memory");
        }
        asm volatile("cp.async.wait_group 2;" ::: "memory");
        asm volatile("membar.cta;" ::: "memory");
        if (lane == 0) stsv32(xp_b, 8u);

        for (int g = 4; g < NBLK; g++) {
            // SAFE overwrite condition (the R14/R15 bug): group g aliases the
            // x-slots of steps 4g-16..4g-13; rows finish READING those before
            // posting step 4g-13, i.e. before pprog reaches 4g-12.
            poll_ge32(pp_b, 4 * g - 12);
            #pragma unroll
            for (int j = 0; j < 4; j++) {
                int l = g * 4 + j;
                uint32_t dst = xs_b + (uint32_t)(l & (XD - 1)) * 1024u + (uint32_t)lane * 16u;
                const char* src = xsrc + (size_t)l * 1024 + lane * 16;
                cpa16(dst, src);
                cpa16(dst + 512u, src + 512);
            }
            if (lane < 4) {
                int l = g * 4 + lane;
                cpa16(f4_b + (uint32_t)(l & (XD - 1)) * 16u, fsrc + l);
            }
            asm volatile("cp.async.commit_group;" ::: "memory");
            asm volatile("cp.async.wait_group 2;" ::: "memory");
            asm volatile("membar.cta;" ::: "memory");
            if (lane == 0) stsv32(xp_b, (unsigned)(4 * g - 4));
        }
        asm volatile("cp.async.wait_group 0;" ::: "memory");
        asm volatile("membar.cta;" ::: "memory");
        if (lane == 0) stsv32(xp_b, (unsigned)SS);

    } else if (wid == 1) {
        // ===================== Z: gather + DSMEM push =====================
        uint32_t raddr = 0;
        {
            uint32_t cb2 = (uint32_t)__cvta_generic_to_shared(&cslot[0][rank]);
            if (lane < CL)
                asm("mapa.shared::cluster.u32 %0,%1,%2;" : "=r"(raddr) : "r"(cb2), "r"(lane));
        }
        for (int t = 0; t < SS; t++) {
            int slot = t & (RZ - 1);
            float z = 0.0f;
            if (lane < 16)
                z = poll_tag64(zv_b + (uint32_t)(slot * 16 + lane) * 8u, (unsigned)(t + 1));
            z = wredux(z);
            if (lane < CL)
                stcl64(raddr + (uint32_t)slot * (CL * 8u), pack_fu(z, (unsigned)(t + 1)));
        }

    } else if (wid == 2) {
        // ===================== P: scalar engine =====================
        const float* db = g_d + (size_t)batch * SS;
        float G = g0v;
        float P = 1.0f;
        float aa = alpha * alpha;
        float pend_f = 1.0f; int pend_mat = -1;
        for (int tau = 0; tau < SS; tau++) {
            // backpressure vs O: keep P <= O+51 so rows (<= P+8) stay inside
            // the 64-deep wv/qring rings. Amortized: one check per 16 steps.
            if ((tau & 15) == 0) poll_ge32(op_b, tau - 36);
            int slot = tau & (RZ - 1);
            uint32_t a = cs_b + (uint32_t)slot * 64u;
            unsigned want = (unsigned)(tau + 1);
            ull p0, p1, p2, p3, p4, p5, p6, p7;
            for (;;) {
                ldsv128(a,       p0, p1);
                ldsv128(a + 16u, p2, p3);
                ldsv128(a + 32u, p4, p5);
                ldsv128(a + 48u, p6, p7);
                if ((unsigned)(p0 >> 32) == want && (unsigned)(p1 >> 32) == want &&
                    (unsigned)(p2 >> 32) == want && (unsigned)(p3 >> 32) == want &&
                    (unsigned)(p4 >> 32) == want && (unsigned)(p5 >> 32) == want &&
                    (unsigned)(p6 >> 32) == want && (unsigned)(p7 >> 32) == want) break;
            }
            float zc = ((__uint_as_float((unsigned)p0) + __uint_as_float((unsigned)p1))
                      + (__uint_as_float((unsigned)p2) + __uint_as_float((unsigned)p3)))
                     + ((__uint_as_float((unsigned)p4) + __uint_as_float((unsigned)p5))
                      + (__uint_as_float((unsigned)p6) + __uint_as_float((unsigned)p7)));
            float Qb = P;
            if (lane == 0) stsv64(qr_b + (uint32_t)(tau & (RWV - 1)) * 8u, pack_fu(Qb, want));
            float y2 = Qb * Qb * zc;
            float d  = __ldg(db + tau);
            float Gn = fmaf(aa, G, d * y2);
            float s  = fminf(15.0f / (sqrtf(Gn) + 1e-6f), 1.0f);
            G = s * s * Gn;
            P = Qb * s;
            if (tau == pend_mat) { P = P / pend_f; pend_mat = -1; }
            if ((tau & 31) == 31 && tau + LAGF <= SS - 1) {
                int jj = tau >> 5;
                pend_f = P;
                pend_mat = tau + LAGF;
                if (lane == 0)
                    stsv64(rf_b + (uint32_t)(jj & 7) * 8u, pack_fu(P, (unsigned)(jj + 1)));
            }
            if (lane == 0) stsv32(pp_b, want);
        }
        if (lane == 0) stsv64(fin_b, pack_fu(P, 0x7fffffffu));

    } else {
        // ===================== O: output writer =====================
        float* outb = out + (size_t)batch * SS * DD + rank * 32 + lane;
        for (int t = 0; t < SS; t++) {
            int slot = t & (RWV - 1);
            float Q = poll_tag64(qr_b + (uint32_t)slot * 8u, (unsigned)(t + 1));
            float w = poll_tag64(wv_b + (uint32_t)(slot * 32 + lane) * 8u, (unsigned)(t + 1));
            if (lane == 0) stsv32(op_b, (unsigned)(t + 1));  // reads done for t
            outb[(size_t)t * DD] = Q * w;
        }
    }
}

// ---------------------------------------------------------------------------
extern "C" void kernel_launch(void* const* d_in, const int* in_sizes, int n_in,
                              void* d_out, int out_size) {
    const float* x         = (const float*)d_in[0];
    const float* M_init    = (const float*)d_in[1];
    const float* eta_raw   = (const float*)d_in[2];
    const float* alpha_raw = (const float*)d_in[3];
    float*       out       = (float*)d_out;

    fused_kernel<<<BB * CL, NTHREADS>>>(x, M_init, eta_raw, alpha_raw, out);
}